// round 6
// baseline (speedup 1.0000x reference)
#include <cuda_runtime.h>
#include <cstdint>

#define USER_NUM 100000
#define ITEM_NUM 100000
#define N_NODES  (USER_NUM + ITEM_NUM)
#define EMB      64
#define N_EDGES  6400000
#define EPS      0.1f

// ---------------- static scratch (no allocations allowed) ----------------
// NOTE: these are only ever referenced from DEVICE code. Passing a __device__
// global as a host-side kernel argument yields the host shadow address, which
// on GB300 (ATS-coherent) silently reads host zeros instead of faulting.
__device__ int2  g_edges[N_EDGES];        // {col, val_bits} sorted by row
__device__ int   g_rowptr[N_NODES + 1];
__device__ int   g_cursor[N_NODES];
__device__ int   g_counts[N_NODES];
__device__ int   g_partials[256];
__device__ float g_egoA[(size_t)N_NODES * EMB];
__device__ float g_egoB[(size_t)N_NODES * EMB];
__device__ int   g_is64;

// ---------------- helpers ----------------
__device__ __forceinline__ int load_idx(const void* p, int i) {
    if (g_is64) return (int)((const long long*)p)[i];
    return ((const int*)p)[i];
}

__device__ __forceinline__ float sgnf(float x) {
    return (x > 0.0f) ? 1.0f : ((x < 0.0f) ? -1.0f : 0.0f);
}

// ---------------- dtype detection (int64 vs int32 indices) ----------------
__global__ void k_detect(const void* rows) {
    const unsigned long long* p = (const unsigned long long*)rows;
    int is64 = 1;
    for (int i = 0; i < 16; i++)
        if ((p[i] >> 32) != 0ULL) is64 = 0;
    g_is64 = is64;
}

// ---------------- CSR build ----------------
__global__ void k_zero_counts() {
    int i = blockIdx.x * blockDim.x + threadIdx.x;
    if (i < N_NODES) g_counts[i] = 0;
}

__global__ void k_hist(const void* rows) {
    int i = blockIdx.x * blockDim.x + threadIdx.x;
    if (i < N_EDGES) {
        int r = load_idx(rows, i);
        atomicAdd(&g_counts[r], 1);
    }
}

// block-level exclusive scan, 1024 threads/block
__global__ void k_scan1() {
    __shared__ int s[1024];
    int t = threadIdx.x;
    int i = blockIdx.x * 1024 + t;
    int v = (i < N_NODES) ? g_counts[i] : 0;
    s[t] = v;
    __syncthreads();
    for (int off = 1; off < 1024; off <<= 1) {
        int add = (t >= off) ? s[t - off] : 0;
        __syncthreads();
        s[t] += add;
        __syncthreads();
    }
    if (i < N_NODES) g_rowptr[i] = s[t] - v;   // exclusive
    if (t == 1023) g_partials[blockIdx.x] = s[t];
}

__global__ void k_scan2(int nblocks) {
    __shared__ int s[256];
    int t = threadIdx.x;
    int v = (t < nblocks) ? g_partials[t] : 0;
    s[t] = v;
    __syncthreads();
    for (int off = 1; off < 256; off <<= 1) {
        int add = (t >= off) ? s[t - off] : 0;
        __syncthreads();
        s[t] += add;
        __syncthreads();
    }
    if (t < nblocks) g_partials[t] = s[t] - v; // exclusive
}

__global__ void k_scan3() {
    int t = threadIdx.x;
    int i = blockIdx.x * 1024 + t;
    if (i < N_NODES) {
        int v = g_rowptr[i] + g_partials[blockIdx.x];
        g_rowptr[i] = v;
        g_cursor[i] = v;
    }
    if (blockIdx.x == 0 && t == 0) g_rowptr[N_NODES] = N_EDGES;
}

__global__ void k_scatter(const void* rows, const void* cols,
                          const float* __restrict__ vals) {
    int i = blockIdx.x * blockDim.x + threadIdx.x;
    if (i < N_EDGES) {
        int r = load_idx(rows, i);
        int c = load_idx(cols, i);
        float v = vals[i];
        int pos = atomicAdd(&g_cursor[r], 1);
        g_edges[pos] = make_int2(c, __float_as_int(v));
    }
}

// ---------------- concat(user, item) -> egoB ----------------
__global__ void k_concat(const float4* __restrict__ user,
                         const float4* __restrict__ item) {
    int i = blockIdx.x * blockDim.x + threadIdx.x;               // float4 index
    const int UQ = USER_NUM * EMB / 4;
    const int TQ = N_NODES * EMB / 4;
    if (i < TQ) {
        float4 v = (i < UQ) ? user[i] : item[i - UQ];
        ((float4*)g_egoB)[i] = v;
    }
}

// ---------------- fused SpMM + noise epilogue ----------------
// One warp per output row. Each lane owns 2 of 64 embedding dims.
// Ping-pong buffers are selected INSIDE the kernel (device-symbol access).
// MODE 0: x=egoB, ego_out=egoA; cl = e; final(acc) = e
// MODE 1: x=egoA, ego_out=egoB; final(acc) += e
// MODE 2: x=egoB;               final = (acc + e) / 3
template <int MODE>
__global__ void __launch_bounds__(256)
k_spmm(const float* __restrict__ noise_k,
       float* __restrict__ out_final, float* __restrict__ out_cl) {
    const float* __restrict__ x = (MODE == 1) ? g_egoA : g_egoB;
    float* ego_out = (MODE == 0) ? g_egoA : g_egoB;

    int gw   = (blockIdx.x * blockDim.x + threadIdx.x) >> 5;   // row
    int lane = threadIdx.x & 31;
    if (gw >= N_NODES) return;

    int start = g_rowptr[gw];
    int end   = g_rowptr[gw + 1];

    float2 acc = make_float2(0.0f, 0.0f);
    for (int base = start; base < end; base += 32) {
        int e = base + lane;
        int2 cv = (e < end) ? g_edges[e] : make_int2(0, 0);
        int n = min(32, end - base);
        #pragma unroll 4
        for (int j = 0; j < n; j++) {
            int   c = __shfl_sync(0xffffffffu, cv.x, j);
            float v = __int_as_float(__shfl_sync(0xffffffffu, cv.y, j));
            float2 xv = *(const float2*)&x[(size_t)c * EMB + lane * 2];
            acc.x = fmaf(v, xv.x, acc.x);
            acc.y = fmaf(v, xv.y, acc.y);
        }
    }

    // sign-perturbed normalized noise: e += sign(e) * (n / ||n||) * eps
    float2 nv = *(const float2*)&noise_k[(size_t)gw * EMB + lane * 2];
    float ss = nv.x * nv.x + nv.y * nv.y;
    #pragma unroll
    for (int o = 16; o; o >>= 1) ss += __shfl_xor_sync(0xffffffffu, ss, o);
    float inv = EPS / fmaxf(sqrtf(ss), 1e-12f);

    float ex = acc.x + sgnf(acc.x) * nv.x * inv;
    float ey = acc.y + sgnf(acc.y) * nv.y * inv;

    size_t o = (size_t)gw * EMB + lane * 2;
    if (MODE == 0) {
        *(float2*)&ego_out[o]   = make_float2(ex, ey);
        *(float2*)&out_cl[o]    = make_float2(ex, ey);
        *(float2*)&out_final[o] = make_float2(ex, ey);
    } else if (MODE == 1) {
        *(float2*)&ego_out[o] = make_float2(ex, ey);
        float2 a = *(const float2*)&out_final[o];
        *(float2*)&out_final[o] = make_float2(a.x + ex, a.y + ey);
    } else {
        float2 a = *(const float2*)&out_final[o];
        const float third = 1.0f / 3.0f;
        *(float2*)&out_final[o] =
            make_float2((a.x + ex) * third, (a.y + ey) * third);
    }
}

// ---------------- launch ----------------
extern "C" void kernel_launch(void* const* d_in, const int* in_sizes, int n_in,
                              void* d_out, int out_size) {
    const float* user  = (const float*)d_in[0];
    const float* item  = (const float*)d_in[1];
    const void*  rows  = d_in[2];
    const void*  cols  = d_in[3];
    const float* vals  = (const float*)d_in[4];
    const float* noise = (const float*)d_in[5];

    float* out_final = (float*)d_out;
    float* out_cl    = (float*)d_out + (size_t)N_NODES * EMB;

    const int NB_SCAN = (N_NODES + 1023) / 1024;     // 196
    const int NB_EDGE = (N_EDGES + 255) / 256;       // 25000
    const int NB_NODE = (N_NODES + 255) / 256;
    const int NB_SPMM = (N_NODES * 32 + 255) / 256;  // warp per row
    const int NB_CAT  = (N_NODES * EMB / 4 + 255) / 256;

    k_detect<<<1, 1>>>(rows);
    k_zero_counts<<<NB_NODE, 256>>>();
    k_hist<<<NB_EDGE, 256>>>(rows);
    k_scan1<<<NB_SCAN, 1024>>>();
    k_scan2<<<1, 256>>>(NB_SCAN);
    k_scan3<<<NB_SCAN, 1024>>>();
    k_scatter<<<NB_EDGE, 256>>>(rows, cols, vals);
    k_concat<<<NB_CAT, 256>>>((const float4*)user, (const float4*)item);

    const size_t NP = (size_t)N_NODES * EMB;
    // layer 0: egoB -> egoA, write cl and acc
    k_spmm<0><<<NB_SPMM, 256>>>(noise + 0 * NP, out_final, out_cl);
    // layer 1: egoA -> egoB, acc += e
    k_spmm<1><<<NB_SPMM, 256>>>(noise + 1 * NP, out_final, out_cl);
    // layer 2: egoB -> (none), final = (acc + e)/3
    k_spmm<2><<<NB_SPMM, 256>>>(noise + 2 * NP, out_final, out_cl);
}

// round 10
// speedup vs baseline: 1.0129x; 1.0129x over previous
#include <cuda_runtime.h>
#include <cstdint>

#define USER_NUM 100000
#define ITEM_NUM 100000
#define N_NODES  (USER_NUM + ITEM_NUM)
#define EMB      64
#define N_EDGES  6400000
#define EPS      0.1f

// ---------------- static scratch (no allocations allowed) ----------------
// Only referenced from DEVICE code (GB300/ATS: host-shadow address trap —
// passing a __device__ symbol as a host-side kernel arg silently reads
// host-BSS zeros over NVLink-C2C instead of faulting).
__device__ int2  g_edges[N_EDGES];                 // {col, val_bits} sorted by row
__device__ int   g_rowptr[N_NODES + 1];
__device__ int   g_cursor[N_NODES];
__device__ int   g_counts[N_NODES];
__device__ int   g_partials[256];
__device__ float g_egoA[(size_t)N_NODES * EMB];
__device__ float g_egoB[(size_t)N_NODES * EMB];
__device__ int   g_is64;

// ---------------- helpers ----------------
__device__ __forceinline__ int load_idx(const void* p, int i) {
    if (g_is64) return (int)((const long long*)p)[i];
    return ((const int*)p)[i];
}

__device__ __forceinline__ float sgnf(float x) {
    return (x > 0.0f) ? 1.0f : ((x < 0.0f) ? -1.0f : 0.0f);
}

// ---------------- dtype detection (int64 vs int32 indices) ----------------
__global__ void k_detect(const void* rows) {
    const unsigned long long* p = (const unsigned long long*)rows;
    int is64 = 1;
    for (int i = 0; i < 16; i++)
        if ((p[i] >> 32) != 0ULL) is64 = 0;
    g_is64 = is64;
}

// ---------------- CSR build ----------------
__global__ void k_zero_counts() {
    int i = blockIdx.x * blockDim.x + threadIdx.x;
    if (i < N_NODES) g_counts[i] = 0;
}

__global__ void k_hist(const void* rows) {
    int i = blockIdx.x * blockDim.x + threadIdx.x;
    if (i < N_EDGES) {
        int r = load_idx(rows, i);
        atomicAdd(&g_counts[r], 1);
    }
}

__global__ void k_scan1() {
    __shared__ int s[1024];
    int t = threadIdx.x;
    int i = blockIdx.x * 1024 + t;
    int v = (i < N_NODES) ? g_counts[i] : 0;
    s[t] = v;
    __syncthreads();
    for (int off = 1; off < 1024; off <<= 1) {
        int add = (t >= off) ? s[t - off] : 0;
        __syncthreads();
        s[t] += add;
        __syncthreads();
    }
    if (i < N_NODES) g_rowptr[i] = s[t] - v;   // exclusive
    if (t == 1023) g_partials[blockIdx.x] = s[t];
}

__global__ void k_scan2(int nblocks) {
    __shared__ int s[256];
    int t = threadIdx.x;
    int v = (t < nblocks) ? g_partials[t] : 0;
    s[t] = v;
    __syncthreads();
    for (int off = 1; off < 256; off <<= 1) {
        int add = (t >= off) ? s[t - off] : 0;
        __syncthreads();
        s[t] += add;
        __syncthreads();
    }
    if (t < nblocks) g_partials[t] = s[t] - v; // exclusive
}

__global__ void k_scan3() {
    int t = threadIdx.x;
    int i = blockIdx.x * 1024 + t;
    if (i < N_NODES) {
        int v = g_rowptr[i] + g_partials[blockIdx.x];
        g_rowptr[i] = v;
        g_cursor[i] = v;
    }
    if (blockIdx.x == 0 && t == 0) g_rowptr[N_NODES] = N_EDGES;
}

__global__ void k_scatter(const void* rows, const void* cols,
                          const float* __restrict__ vals) {
    int i = blockIdx.x * blockDim.x + threadIdx.x;
    if (i < N_EDGES) {
        int r = load_idx(rows, i);
        int c = load_idx(cols, i);
        float v = vals[i];
        int pos = atomicAdd(&g_cursor[r], 1);
        g_edges[pos] = make_int2(c, __float_as_int(v));
    }
}

// ---------------- concat(user, item) -> egoB ----------------
__global__ void k_concat(const float4* __restrict__ user,
                         const float4* __restrict__ item) {
    int i = blockIdx.x * blockDim.x + threadIdx.x;               // float4 index
    const int UQ = USER_NUM * EMB / 4;
    const int TQ = N_NODES * EMB / 4;
    if (i < TQ) {
        float4 v = (i < UQ) ? user[i] : item[i - UQ];
        ((float4*)g_egoB)[i] = v;
    }
}

// ---------------- fused SpMM + noise epilogue ----------------
// One warp per row. The two HALF-WARPS process two edges of the row
// concurrently: lane owns 4 dims (float4), 16 lanes cover EMB=64.
// Edge (col,val) staged via smem, read back with broadcast LDS.
// Per 2 edges: ~1 LDS + 1 LDG.128 + 4 FFMA warp-instructions.
// MODE 0: x=egoB, out=egoA; cl = e; final(acc) = e
// MODE 1: x=egoA, out=egoB; final(acc) += e
// MODE 2: x=egoB;           final = (acc + e) / 3
template <int MODE>
__global__ void __launch_bounds__(256)
k_spmm(const float4* __restrict__ noise_k,
       float4* __restrict__ out_final, float4* __restrict__ out_cl) {
    const float4* __restrict__ x =
        (const float4*)((MODE == 1) ? g_egoA : g_egoB);
    float4* ego_out = (float4*)((MODE == 0) ? g_egoA : g_egoB);

    __shared__ int2 s_edges[8][32];                    // 8 warps/block

    int wlocal = threadIdx.x >> 5;
    int gw     = (blockIdx.x * blockDim.x + threadIdx.x) >> 5;   // row
    int lane   = threadIdx.x & 31;
    int hl     = lane & 15;                            // lane within half-warp
    int half   = lane >> 4;                            // 0 or 1
    if (gw >= N_NODES) return;

    int start = g_rowptr[gw];
    int end   = g_rowptr[gw + 1];

    float4 acc = make_float4(0.0f, 0.0f, 0.0f, 0.0f);

    for (int base = start; base < end; base += 32) {
        int e = base + lane;
        if (e < end) s_edges[wlocal][lane] = g_edges[e];
        __syncwarp();
        int n = min(32, end - base);
        #pragma unroll 2
        for (int j = 0; j < n; j += 2) {
            int  jj = j + half;                        // half0: j, half1: j+1
            int2 cv = (jj < n) ? s_edges[wlocal][jj] : make_int2(0, 0);
            float v = __int_as_float(cv.y);            // 0.0f when jj >= n
            float4 xv = x[(size_t)cv.x * 16 + hl];
            acc.x = fmaf(v, xv.x, acc.x);
            acc.y = fmaf(v, xv.y, acc.y);
            acc.z = fmaf(v, xv.z, acc.z);
            acc.w = fmaf(v, xv.w, acc.w);
        }
        __syncwarp();
    }

    // merge the two half-warp partials (same dims, different edge subsets)
    acc.x += __shfl_xor_sync(0xffffffffu, acc.x, 16);
    acc.y += __shfl_xor_sync(0xffffffffu, acc.y, 16);
    acc.z += __shfl_xor_sync(0xffffffffu, acc.z, 16);
    acc.w += __shfl_xor_sync(0xffffffffu, acc.w, 16);

    // epilogue on lanes 0-15: e += sign(e) * (n / ||n||) * eps
    if (half == 0) {
        float4 nv = noise_k[(size_t)gw * 16 + hl];
        float ss = nv.x * nv.x + nv.y * nv.y + nv.z * nv.z + nv.w * nv.w;
        #pragma unroll
        for (int o = 8; o; o >>= 1) ss += __shfl_xor_sync(0x0000ffffu, ss, o);
        float inv = EPS / fmaxf(sqrtf(ss), 1e-12f);

        float4 ev;
        ev.x = acc.x + sgnf(acc.x) * nv.x * inv;
        ev.y = acc.y + sgnf(acc.y) * nv.y * inv;
        ev.z = acc.z + sgnf(acc.z) * nv.z * inv;
        ev.w = acc.w + sgnf(acc.w) * nv.w * inv;

        size_t o = (size_t)gw * 16 + hl;
        if (MODE == 0) {
            ego_out[o]   = ev;
            out_cl[o]    = ev;
            out_final[o] = ev;
        } else if (MODE == 1) {
            ego_out[o] = ev;
            float4 a = out_final[o];
            out_final[o] = make_float4(a.x + ev.x, a.y + ev.y,
                                       a.z + ev.z, a.w + ev.w);
        } else {
            float4 a = out_final[o];
            const float third = 1.0f / 3.0f;
            out_final[o] = make_float4((a.x + ev.x) * third,
                                       (a.y + ev.y) * third,
                                       (a.z + ev.z) * third,
                                       (a.w + ev.w) * third);
        }
    }
}

// ---------------- launch ----------------
extern "C" void kernel_launch(void* const* d_in, const int* in_sizes, int n_in,
                              void* d_out, int out_size) {
    const float* user  = (const float*)d_in[0];
    const float* item  = (const float*)d_in[1];
    const void*  rows  = d_in[2];
    const void*  cols  = d_in[3];
    const float* vals  = (const float*)d_in[4];
    const float* noise = (const float*)d_in[5];

    float4* out_final = (float4*)d_out;
    float4* out_cl    = (float4*)d_out + (size_t)N_NODES * (EMB / 4);

    const int NB_SCAN = (N_NODES + 1023) / 1024;     // 196
    const int NB_EDGE = (N_EDGES + 255) / 256;       // 25000
    const int NB_NODE = (N_NODES + 255) / 256;
    const int NB_SPMM = (N_NODES * 32 + 255) / 256;  // warp per row
    const int NB_CAT  = (N_NODES * EMB / 4 + 255) / 256;

    k_detect<<<1, 1>>>(rows);
    k_zero_counts<<<NB_NODE, 256>>>();
    k_hist<<<NB_EDGE, 256>>>(rows);
    k_scan1<<<NB_SCAN, 1024>>>();
    k_scan2<<<1, 256>>>(NB_SCAN);
    k_scan3<<<NB_SCAN, 1024>>>();
    k_scatter<<<NB_EDGE, 256>>>(rows, cols, vals);
    k_concat<<<NB_CAT, 256>>>((const float4*)user, (const float4*)item);

    const size_t NPQ = (size_t)N_NODES * (EMB / 4);  // float4 elements per layer
    const float4* noise4 = (const float4*)noise;
    k_spmm<0><<<NB_SPMM, 256>>>(noise4 + 0 * NPQ, out_final, out_cl);
    k_spmm<1><<<NB_SPMM, 256>>>(noise4 + 1 * NPQ, out_final, out_cl);
    k_spmm<2><<<NB_SPMM, 256>>>(noise4 + 2 * NPQ, out_final, out_cl);
}

// round 11
// speedup vs baseline: 1.1744x; 1.1595x over previous
#include <cuda_runtime.h>
#include <cstdint>

#define USER_NUM 100000
#define ITEM_NUM 100000
#define N_NODES  (USER_NUM + ITEM_NUM)
#define EMB      64
#define N_EDGES  6400000
#define EPS      0.1f

// ---------------- static scratch (no allocations allowed) ----------------
// Only referenced from DEVICE code (GB300/ATS: host-shadow address trap —
// passing a __device__ symbol as a host-side kernel arg silently reads
// host-BSS zeros over NVLink-C2C instead of faulting).
__device__ int2  g_edges[N_EDGES];                 // {col, val_bits} sorted by row
__device__ int   g_rowptr[N_NODES + 1];
__device__ int   g_cursor[N_NODES];
__device__ int   g_counts[N_NODES];
__device__ int   g_partials[256];
__device__ float g_egoA[(size_t)N_NODES * EMB];
__device__ float g_egoB[(size_t)N_NODES * EMB];
__device__ int   g_is64;

// ---------------- helpers ----------------
__device__ __forceinline__ int load_idx(const void* p, int i) {
    if (g_is64) return (int)((const long long*)p)[i];
    return ((const int*)p)[i];
}

__device__ __forceinline__ float sgnf(float x) {
    return (x > 0.0f) ? 1.0f : ((x < 0.0f) ? -1.0f : 0.0f);
}

// ---------------- dtype detection (int64 vs int32 indices) ----------------
__global__ void k_detect(const void* rows) {
    const unsigned long long* p = (const unsigned long long*)rows;
    int is64 = 1;
    for (int i = 0; i < 16; i++)
        if ((p[i] >> 32) != 0ULL) is64 = 0;
    g_is64 = is64;
}

// ---------------- CSR build ----------------
__global__ void k_zero_counts() {
    int i = blockIdx.x * blockDim.x + threadIdx.x;
    if (i < N_NODES) g_counts[i] = 0;
}

__global__ void k_hist(const void* rows) {
    int i = blockIdx.x * blockDim.x + threadIdx.x;
    if (i < N_EDGES) {
        int r = load_idx(rows, i);
        atomicAdd(&g_counts[r], 1);
    }
}

__global__ void k_scan1() {
    __shared__ int s[1024];
    int t = threadIdx.x;
    int i = blockIdx.x * 1024 + t;
    int v = (i < N_NODES) ? g_counts[i] : 0;
    s[t] = v;
    __syncthreads();
    for (int off = 1; off < 1024; off <<= 1) {
        int add = (t >= off) ? s[t - off] : 0;
        __syncthreads();
        s[t] += add;
        __syncthreads();
    }
    if (i < N_NODES) g_rowptr[i] = s[t] - v;   // exclusive
    if (t == 1023) g_partials[blockIdx.x] = s[t];
}

__global__ void k_scan2(int nblocks) {
    __shared__ int s[256];
    int t = threadIdx.x;
    int v = (t < nblocks) ? g_partials[t] : 0;
    s[t] = v;
    __syncthreads();
    for (int off = 1; off < 256; off <<= 1) {
        int add = (t >= off) ? s[t - off] : 0;
        __syncthreads();
        s[t] += add;
        __syncthreads();
    }
    if (t < nblocks) g_partials[t] = s[t] - v; // exclusive
}

__global__ void k_scan3() {
    int t = threadIdx.x;
    int i = blockIdx.x * 1024 + t;
    if (i < N_NODES) {
        int v = g_rowptr[i] + g_partials[blockIdx.x];
        g_rowptr[i] = v;
        g_cursor[i] = v;
    }
    if (blockIdx.x == 0 && t == 0) g_rowptr[N_NODES] = N_EDGES;
}

__global__ void k_scatter(const void* rows, const void* cols,
                          const float* __restrict__ vals) {
    int i = blockIdx.x * blockDim.x + threadIdx.x;
    if (i < N_EDGES) {
        int r = load_idx(rows, i);
        int c = load_idx(cols, i);
        float v = vals[i];
        int pos = atomicAdd(&g_cursor[r], 1);
        g_edges[pos] = make_int2(c, __float_as_int(v));
    }
}

// ---------------- concat(user, item) -> egoB ----------------
__global__ void k_concat(const float4* __restrict__ user,
                         const float4* __restrict__ item) {
    int i = blockIdx.x * blockDim.x + threadIdx.x;               // float4 index
    const int UQ = USER_NUM * EMB / 4;
    const int TQ = N_NODES * EMB / 4;
    if (i < TQ) {
        float4 v = (i < UQ) ? user[i] : item[i - UQ];
        ((float4*)g_egoB)[i] = v;
    }
}

// ---------------- fused SpMM + noise epilogue ----------------
// One warp per row; the two half-warps process two edges concurrently.
// Lane owns 4 dims (float4); 16 lanes cover EMB=64.
// FULL 32-edge batches take a fully-unrolled, predicate-free path so ptxas
// can front-batch all 16 independent LDG.128s (MLP ~16); the tail (<32
// edges) takes a short predicated path. Edge (col,val) staged via smem.
// MODE 0: x=egoB, out=egoA; cl = e; final(acc) = e
// MODE 1: x=egoA, out=egoB; final(acc) += e
// MODE 2: x=egoB;           final = (acc + e) / 3
template <int MODE>
__global__ void __launch_bounds__(256)
k_spmm(const float4* __restrict__ noise_k,
       float4* __restrict__ out_final, float4* __restrict__ out_cl) {
    const float4* __restrict__ x =
        (const float4*)((MODE == 1) ? g_egoA : g_egoB);
    float4* ego_out = (float4*)((MODE == 0) ? g_egoA : g_egoB);

    __shared__ int2 s_edges[8][32];                    // 8 warps/block

    int wlocal = threadIdx.x >> 5;
    int gw     = (blockIdx.x * blockDim.x + threadIdx.x) >> 5;   // row
    int lane   = threadIdx.x & 31;
    int hl     = lane & 15;                            // lane within half-warp
    int half   = lane >> 4;                            // 0 or 1
    if (gw >= N_NODES) return;

    int start = g_rowptr[gw];
    int end   = g_rowptr[gw + 1];

    float4 acc = make_float4(0.0f, 0.0f, 0.0f, 0.0f);

    int base = start;
    // ---- full 32-edge batches: no predicates, full unroll, high MLP ----
    for (; base + 32 <= end; base += 32) {
        s_edges[wlocal][lane] = g_edges[base + lane];
        __syncwarp();
        #pragma unroll
        for (int j = 0; j < 32; j += 2) {
            int2  cv = s_edges[wlocal][j + half];
            float v  = __int_as_float(cv.y);
            float4 xv = x[(size_t)cv.x * 16 + hl];
            acc.x = fmaf(v, xv.x, acc.x);
            acc.y = fmaf(v, xv.y, acc.y);
            acc.z = fmaf(v, xv.z, acc.z);
            acc.w = fmaf(v, xv.w, acc.w);
        }
        __syncwarp();
    }
    // ---- tail (< 32 edges) ----
    if (base < end) {
        int e = base + lane;
        if (e < end) s_edges[wlocal][lane] = g_edges[e];
        __syncwarp();
        int n = end - base;
        #pragma unroll 4
        for (int j = 0; j < n; j += 2) {
            int  jj = j + half;
            int2 cv = (jj < n) ? s_edges[wlocal][jj] : make_int2(0, 0);
            float v = __int_as_float(cv.y);            // 0.0f when jj >= n
            float4 xv = x[(size_t)cv.x * 16 + hl];
            acc.x = fmaf(v, xv.x, acc.x);
            acc.y = fmaf(v, xv.y, acc.y);
            acc.z = fmaf(v, xv.z, acc.z);
            acc.w = fmaf(v, xv.w, acc.w);
        }
        __syncwarp();
    }

    // merge the two half-warp partials (same dims, different edge subsets)
    acc.x += __shfl_xor_sync(0xffffffffu, acc.x, 16);
    acc.y += __shfl_xor_sync(0xffffffffu, acc.y, 16);
    acc.z += __shfl_xor_sync(0xffffffffu, acc.z, 16);
    acc.w += __shfl_xor_sync(0xffffffffu, acc.w, 16);

    // epilogue on lanes 0-15: e += sign(e) * (n / ||n||) * eps
    if (half == 0) {
        float4 nv = noise_k[(size_t)gw * 16 + hl];
        float ss = nv.x * nv.x + nv.y * nv.y + nv.z * nv.z + nv.w * nv.w;
        #pragma unroll
        for (int o = 8; o; o >>= 1) ss += __shfl_xor_sync(0x0000ffffu, ss, o);
        float inv = EPS / fmaxf(sqrtf(ss), 1e-12f);

        float4 ev;
        ev.x = acc.x + sgnf(acc.x) * nv.x * inv;
        ev.y = acc.y + sgnf(acc.y) * nv.y * inv;
        ev.z = acc.z + sgnf(acc.z) * nv.z * inv;
        ev.w = acc.w + sgnf(acc.w) * nv.w * inv;

        size_t o = (size_t)gw * 16 + hl;
        if (MODE == 0) {
            ego_out[o]   = ev;
            out_cl[o]    = ev;
            out_final[o] = ev;
        } else if (MODE == 1) {
            ego_out[o] = ev;
            float4 a = out_final[o];
            out_final[o] = make_float4(a.x + ev.x, a.y + ev.y,
                                       a.z + ev.z, a.w + ev.w);
        } else {
            float4 a = out_final[o];
            const float third = 1.0f / 3.0f;
            out_final[o] = make_float4((a.x + ev.x) * third,
                                       (a.y + ev.y) * third,
                                       (a.z + ev.z) * third,
                                       (a.w + ev.w) * third);
        }
    }
}

// ---------------- launch ----------------
extern "C" void kernel_launch(void* const* d_in, const int* in_sizes, int n_in,
                              void* d_out, int out_size) {
    const float* user  = (const float*)d_in[0];
    const float* item  = (const float*)d_in[1];
    const void*  rows  = d_in[2];
    const void*  cols  = d_in[3];
    const float* vals  = (const float*)d_in[4];
    const float* noise = (const float*)d_in[5];

    float4* out_final = (float4*)d_out;
    float4* out_cl    = (float4*)d_out + (size_t)N_NODES * (EMB / 4);

    const int NB_SCAN = (N_NODES + 1023) / 1024;     // 196
    const int NB_EDGE = (N_EDGES + 255) / 256;       // 25000
    const int NB_NODE = (N_NODES + 255) / 256;
    const int NB_SPMM = (N_NODES * 32 + 255) / 256;  // warp per row
    const int NB_CAT  = (N_NODES * EMB / 4 + 255) / 256;

    k_detect<<<1, 1>>>(rows);
    k_zero_counts<<<NB_NODE, 256>>>();
    k_hist<<<NB_EDGE, 256>>>(rows);
    k_scan1<<<NB_SCAN, 1024>>>();
    k_scan2<<<1, 256>>>(NB_SCAN);
    k_scan3<<<NB_SCAN, 1024>>>();
    k_scatter<<<NB_EDGE, 256>>>(rows, cols, vals);
    k_concat<<<NB_CAT, 256>>>((const float4*)user, (const float4*)item);

    const size_t NPQ = (size_t)N_NODES * (EMB / 4);  // float4 elements per layer
    const float4* noise4 = (const float4*)noise;
    k_spmm<0><<<NB_SPMM, 256>>>(noise4 + 0 * NPQ, out_final, out_cl);
    k_spmm<1><<<NB_SPMM, 256>>>(noise4 + 1 * NPQ, out_final, out_cl);
    k_spmm<2><<<NB_SPMM, 256>>>(noise4 + 2 * NPQ, out_final, out_cl);
}